// round 17
// baseline (speedup 1.0000x reference)
#include <cuda_runtime.h>
#include <cuda_fp16.h>
#include <cstdint>

// Problem dims
#define B   64
#define NN  2048
#define NC  32
#define IC  16
#define OC  32
#define KO  (NC * OC)        // 1024
#define NCHUNK 64            // CTAs per batch for k_iter
#define NPB (NN / NCHUNK)    // 32 nodes per CTA
#define SNODES 4             // nodes per stage (1 per warp)
#define NSTAGES (NPB / SNODES) // 8 stages
#define STAGE_B (SNODES * KO * 2) // 8192 bytes per stage

// k_priors_s0 tiling
#define PKG 8                 // k-groups (4 k each)
#define PNG 128               // node-groups
#define PNODES 16             // nodes per block

// ---------------- scratch (device globals; no runtime allocation) ----------
__device__ __half g_priors[(size_t)B * NN * KO];   // 268 MB fp16 priors [b][n][k][o]
__device__ float  g_logits[(size_t)B * NN * NC];   // 16 MB  logits  [b][n][k]
__device__ float  g_s[B * KO];                     // s accumulator (zeroed by squash)
__device__ float  g_out[B * KO];                   // current outputs v_i

// ---------------- PTX helpers ----------------------------------------------
__device__ __forceinline__ uint32_t s2u(const void* p) {
    return (uint32_t)__cvta_generic_to_shared(p);
}
__device__ __forceinline__ void mb_init(uint32_t a, uint32_t cnt) {
    asm volatile("mbarrier.init.shared.b64 [%0], %1;" :: "r"(a), "r"(cnt) : "memory");
}
__device__ __forceinline__ void mb_expect(uint32_t a, uint32_t bytes) {
    asm volatile("mbarrier.arrive.expect_tx.shared.b64 _, [%0], %1;"
                 :: "r"(a), "r"(bytes) : "memory");
}
__device__ __forceinline__ void mb_arrive(uint32_t a) {
    asm volatile("mbarrier.arrive.shared.b64 _, [%0];" :: "r"(a) : "memory");
}
__device__ __forceinline__ void mb_wait(uint32_t a, uint32_t parity) {
    asm volatile(
        "{\n\t.reg .pred P;\n"
        "W%=:\n\t"
        "mbarrier.try_wait.parity.acquire.cta.shared::cta.b64 P, [%0], %1, 0x989680;\n\t"
        "@P bra D%=;\n\t"
        "bra W%=;\n"
        "D%=:\n\t}"
        :: "r"(a), "r"(parity) : "memory");
}
__device__ __forceinline__ void bulk_g2s(uint32_t dst_s, const void* src_g,
                                         uint32_t bytes, uint32_t mbar_s) {
    asm volatile(
        "cp.async.bulk.shared::cta.global.mbarrier::complete_tx::bytes "
        "[%0], [%1], %2, [%3];"
        :: "r"(dst_s), "l"(src_g), "r"(bytes), "r"(mbar_s) : "memory");
}

// ---------------- pass 0: priors + FUSED s0 --------------------------------
// Grid (PKG=8 k-groups, PNG=128 node-groups), 256 threads, 2 blocks/SM.
// Block owns 16 nodes x 4 k x all 64 b x 32 o. W partitioned by (n,k): read
// exactly once from DRAM. Thread = (bq=warp, k2, og): computes priors via
// f32x2 FMA (W resident in regs per node), stores fp16 priors, and
// accumulates its fp32 s0-partial into a conflict-free padded smem tile
// (lane bank = 8*k2+og, all distinct). One atomicAdd flush per block
// (8.4M RED ops total ~12us) -> iter0's 268MB read pass is ELIMINATED.
__global__ void __launch_bounds__(256, 2) k_priors_s0(const float* __restrict__ x,
                                                      const float* __restrict__ w) {
    const int kg = blockIdx.x;            // 0..7
    const int ng = blockIdx.y;            // 0..127
    const int t  = threadIdx.x;
    const int bq = t >> 5;                // warp id: b-octet 0..7
    const int k2 = (t >> 3) & 3;          // 0..3
    const int og = t & 7;                 // 0..7 (4 consecutive o)
    const int k  = kg * 4 + k2;

    __shared__ unsigned long long sx[B][IC];        // 8KB, x packed (v,v)
    __shared__ float s_acc[8 * 4 * 8 * 33];         // [b'][k2][og][bq*4+oo pad33]

    for (int i = t; i < 8 * 4 * 8 * 33; i += 256) s_acc[i] = 0.f;

#pragma unroll 1
    for (int nd = 0; nd < PNODES; nd++) {
        const int n = ng * PNODES + nd;
        __syncthreads();                  // sx reuse ordering (+ covers zeroing)
        for (int idx = t; idx < B * IC; idx += 256) {
            int bb = idx >> 4, i = idx & 15;
            float v = x[((size_t)bb * NN + n) * IC + i];
            unsigned long long pv;
            asm("mov.b64 %0, {%1, %2};" : "=l"(pv) : "f"(v), "f"(v));
            sx[bb][i] = pv;
        }
        __syncthreads();

        // W slice for (n, k, og): 16 i x 4 o -> 32 packed pairs in regs
        unsigned long long wp[2 * IC];
        const float* wbase = w + (((size_t)n * NC + k) * IC) * OC + og * 4;
#pragma unroll
        for (int i = 0; i < IC; i++) {
            ulonglong2 v = *(const ulonglong2*)(wbase + (size_t)i * OC);
            wp[2 * i]     = v.x;
            wp[2 * i + 1] = v.y;
        }

#pragma unroll 1
        for (int bb = 0; bb < 8; bb++) {
            const int b = bq * 8 + bb;
            unsigned long long a0 = 0ull, a1 = 0ull;
#pragma unroll
            for (int i = 0; i < IC; i++) {
                unsigned long long xv = sx[b][i];
                asm("fma.rn.f32x2 %0, %1, %2, %0;" : "+l"(a0) : "l"(xv), "l"(wp[2 * i]));
                asm("fma.rn.f32x2 %0, %1, %2, %0;" : "+l"(a1) : "l"(xv), "l"(wp[2 * i + 1]));
            }
            float f0, f1, f2, f3;
            asm("mov.b64 {%0, %1}, %2;" : "=f"(f0), "=f"(f1) : "l"(a0));
            asm("mov.b64 {%0, %1}, %2;" : "=f"(f2), "=f"(f3) : "l"(a1));

            __half2 h01 = __floats2half2_rn(f0, f1);
            __half2 h23 = __floats2half2_rn(f2, f3);
            uint2 st;
            st.x = *(const unsigned int*)&h01;
            st.y = *(const unsigned int*)&h23;
            *(uint2*)(g_priors + ((size_t)b * NN + n) * KO + k * OC + og * 4) = st;

            float* ap = &s_acc[(((bb * 4 + k2) * 8 + og) * 33) + bq * 4];
            ap[0] += f0; ap[1] += f1; ap[2] += f2; ap[3] += f3;
        }
    }

    // flush s0 partials (prob = 1/NC uniform)
#pragma unroll 1
    for (int bb = 0; bb < 8; bb++) {
        const int b = bq * 8 + bb;
        const float* ap = &s_acc[(((bb * 4 + k2) * 8 + og) * 33) + bq * 4];
        float* gp = g_s + b * KO + k * OC + og * 4;
        atomicAdd(gp + 0, ap[0] * (1.f / NC));
        atomicAdd(gp + 1, ap[1] * (1.f / NC));
        atomicAdd(gp + 2, ap[2] * (1.f / NC));
        atomicAdd(gp + 3, ap[3] * (1.f / NC));
    }
}

// ---------------- routing pass: TMA bulk producer / warp consumers ---------
// Grid: (NCHUNK, B), 128-thr CTAs, 6 CTAs/SM. tid0 streams priors via
// cp.async.bulk into a 3-slot smem ring; 4 warps consume 1 node/warp/stage.
// ITER==1 consumes stages in REVERSE (k_priors' L2-resident tail first) and
// stores logits; ITER==2 runs FORWARD (catches iter1's L2 tail) and adds the
// stored logits (4KB block bulk-loaded once).
template <int ITER>
__global__ void __launch_bounds__(128, 6) k_iter() {
    __shared__ __align__(128) char sbuf[3][STAGE_B];       // 24KB ring
    __shared__ float   s_s[NC * 33];                       // padded partials
    __shared__ __half2 s_outh[NC][17];                     // out rows (half2)
    __shared__ float   s_lg[NPB * NC];                     // 4KB logits (ITER2)
    __shared__ __align__(8) unsigned long long barmem[7];  // full[3],empty[3],lg

    const int tid  = threadIdx.x;
    const int b    = blockIdx.y;
    const int w    = tid >> 5;             // warp 0..3
    const int lane = tid & 31;
    const int m    = lane >> 2;            // k-subindex 0..7
    const int c    = lane & 3;             // o-slice 0..3

    const uint32_t fullb  = s2u(&barmem[0]);
    const uint32_t emptyb = s2u(&barmem[3]);
    const uint32_t lgbar  = s2u(&barmem[6]);

    if (tid == 0) {
#pragma unroll
        for (int i = 0; i < 3; i++) {
            mb_init(fullb + 8 * i, 1);
            mb_init(emptyb + 8 * i, 4);
        }
        mb_init(lgbar, 1);
    }

    for (int idx = tid; idx < NC * 33; idx += 128) s_s[idx] = 0.f;
    {
        const float2* op = (const float2*)g_out + b * (KO / 2);
        for (int idx = tid; idx < KO / 2; idx += 128) {
            int k = idx >> 4, r = idx & 15;
            s_outh[k][r] = __float22half2_rn(op[idx]);
        }
    }
    __syncthreads();

    const int n0 = blockIdx.x * NPB;
    const __half* pbase = g_priors + ((size_t)b * NN + n0) * KO;

    // stage order: ITER1 reverse (L2 tail of k_priors), ITER2 forward
#define CH(s) ((ITER == 1) ? (NSTAGES - 1 - (s)) : (s))

    if (tid == 0) {
        if (ITER == 2) {
            mb_expect(lgbar, NPB * NC * 4);
            bulk_g2s(s2u(s_lg), g_logits + ((size_t)b * NN + n0) * NC,
                     NPB * NC * 4, lgbar);
        }
#pragma unroll
        for (int s = 0; s < 3; s++) {
            mb_expect(fullb + 8 * s, STAGE_B);
            bulk_g2s(s2u(sbuf[s]), pbase + (size_t)CH(s) * SNODES * KO,
                     STAGE_B, fullb + 8 * s);
        }
    }
    if (ITER == 2) mb_wait(lgbar, 0);

    float acc[4][8];
#pragma unroll
    for (int j = 0; j < 4; j++)
#pragma unroll
        for (int e = 0; e < 8; e++) acc[j][e] = 0.f;

#pragma unroll 1
    for (int s = 0; s < NSTAGES; s++) {
        const int slot = s % 3;
        mb_wait(fullb + 8 * slot, (uint32_t)((s / 3) & 1));

        const int chunk = CH(s);
        const int node  = chunk * SNODES + w;
        const char* nb  = sbuf[slot] + w * (KO * 2);

        uint4 uj[4];
#pragma unroll
        for (int j = 0; j < 4; j++)
            uj[j] = *(const uint4*)(nb + j * 512 + lane * 16);

        float dpar[4];
#pragma unroll
        for (int j = 0; j < 4; j++) {
            const __half2* hp = (const __half2*)&uj[j];
            __half2 dh = __float2half2_rn(0.f);
#pragma unroll
            for (int q = 0; q < 4; q++)
                dh = __hfma2(hp[q], s_outh[j * 8 + m][4 * c + q], dh);
            float2 f = __half22float2(dh);
            dpar[j] = f.x + f.y;
        }
#pragma unroll
        for (int j = 0; j < 4; j++) {
            dpar[j] += __shfl_xor_sync(0xffffffffu, dpar[j], 1);
            dpar[j] += __shfl_xor_sync(0xffffffffu, dpar[j], 2);
        }

        if (ITER == 1 && c == 0) {
            float* lp = g_logits + ((size_t)b * NN + n0 + node) * NC + m;
#pragma unroll
            for (int j = 0; j < 4; j++) lp[j * 8] = dpar[j];
        }

        float e[4], S = 0.f;
#pragma unroll
        for (int j = 0; j < 4; j++) {
            float logit = dpar[j];
            if (ITER == 2) logit += s_lg[node * NC + j * 8 + m];
            e[j] = __expf(logit);
            S += e[j];
        }
        S += __shfl_xor_sync(0xffffffffu, S, 4);
        S += __shfl_xor_sync(0xffffffffu, S, 8);
        S += __shfl_xor_sync(0xffffffffu, S, 16);
        const float inv = __fdividef(1.f, S);

#pragma unroll
        for (int j = 0; j < 4; j++) {
            const float pr = e[j] * inv;
            const __half2* hp = (const __half2*)&uj[j];
#pragma unroll
            for (int q = 0; q < 4; q++) {
                float2 pf = __half22float2(hp[q]);
                acc[j][2 * q]     = fmaf(pr, pf.x, acc[j][2 * q]);
                acc[j][2 * q + 1] = fmaf(pr, pf.y, acc[j][2 * q + 1]);
            }
        }

        __syncwarp();
        if (lane == 0) mb_arrive(emptyb + 8 * slot);

        if (tid == 0 && s + 3 < NSTAGES) {
            mb_wait(emptyb + 8 * slot, (uint32_t)((s / 3) & 1));
            mb_expect(fullb + 8 * slot, STAGE_B);
            bulk_g2s(s2u(sbuf[slot]), pbase + (size_t)CH(s + 3) * SNODES * KO,
                     STAGE_B, fullb + 8 * slot);
        }
    }
#undef CH

#pragma unroll
    for (int j = 0; j < 4; j++)
#pragma unroll
        for (int e = 0; e < 8; e++)
            atomicAdd(&s_s[(j * 8 + m) * 33 + c * 8 + e], acc[j][e]);
    __syncthreads();

    for (int idx = tid; idx < KO; idx += 128)
        atomicAdd(&g_s[b * KO + idx], s_s[(idx >> 5) * 33 + (idx & 31)]);
}

// ---------------- squash: v = (|s|^2/(1+|s|^2)) * s/|s| -------------------
// Grid: (NC, B), 32 threads (lane = o). Also re-zeros g_s so the next pass /
// next graph replay starts clean (keeps kernel_launch deterministic).
template <bool FINAL>
__global__ void k_squash(float* __restrict__ dst) {
    const int k = blockIdx.x, b = blockIdx.y, o = threadIdx.x;
    const int idx = b * KO + k * OC + o;
    float v = g_s[idx];
    g_s[idx] = 0.f;
    float sq = v * v;
#pragma unroll
    for (int off = 16; off > 0; off >>= 1)
        sq += __shfl_xor_sync(0xffffffffu, sq, off);
    float scale = sqrtf(sq) / (1.f + sq);   // = (sq/(1+sq)) / sqrt(sq)
    float out = v * scale;
    if (FINAL) dst[idx] = out;
    else       g_out[idx] = out;
}

// ---------------- launch ----------------------------------------------------
extern "C" void kernel_launch(void* const* d_in, const int* in_sizes, int n_in,
                              void* d_out, int out_size) {
    const float* x = (const float*)d_in[0];          // [B, NN, IC]
    const float* w = (const float*)d_in[1];          // [NN, NC, IC, OC]
    float* out = (float*)d_out;                      // [B, 1, NC, OC]

    // Carveout hints (capture-safe, idempotent): iters need 6x~35KB, priors 2x~42KB.
    cudaFuncSetAttribute(k_iter<1>, cudaFuncAttributePreferredSharedMemoryCarveout, 100);
    cudaFuncSetAttribute(k_iter<2>, cudaFuncAttributePreferredSharedMemoryCarveout, 100);
    cudaFuncSetAttribute(k_priors_s0, cudaFuncAttributePreferredSharedMemoryCarveout, 100);

    // priors + fused s0 (replaces k_priors AND k_iter<0>)
    k_priors_s0<<<dim3(PKG, PNG), 256>>>(x, w);
    k_squash<false><<<dim3(NC, B), 32>>>(nullptr);

    k_iter<1><<<dim3(NCHUNK, B), 128>>>();
    k_squash<false><<<dim3(NC, B), 32>>>(nullptr);

    k_iter<2><<<dim3(NCHUNK, B), 128>>>();
    k_squash<true><<<dim3(NC, B), 32>>>(out);
}